// round 11
// baseline (speedup 1.0000x reference)
#include <cuda_runtime.h>
#include <cuda_fp16.h>
#include <cstdint>

// SimpleGAT reduces exactly to out = inputs @ W (softmax over a broadcast-
// constant axis is uniform; the einsum multiplies H by sum_k(alpha)==1).
// fp32 GEMM M=131072, N=256, K=256 via mma.sync fp16 (base sm_103 target).
// Pure fp16 single-term scheme (calibrated rel_err 2.94e-4 vs 1e-3 gate).
// R10: occupancy push. BM 128->64 (warp tile 16x64, 32 acc regs), smem
//      60KB/CTA -> 3 CTAs/SM (24 warps, occ 37.5%) for latency hiding;
//      R9 showed nothing saturated at 16 warps/SM.

namespace cfg {
constexpr int KDIM = 256, NDIM = 256;
constexpr int BM = 64, BN = 128, KC = 32;
constexpr int NT = 256;                         // 8 warps (4 M x 2 N)
constexpr int NCHUNK = KDIM / KC;               // 8
constexpr int A_STRIDE_B = 160;                 // 40 floats: conflict-free LDS.64
constexpr uint32_t A_STAGE = 64u * A_STRIDE_B;  // 10240 B, 3 stages
constexpr int W_STRIDE_B = 80;                  // 32 fp16 + 16B pad: conflict-free LDSM
constexpr uint32_t W_STAGE = 128u * W_STRIDE_B; // 10240 B, 3 stages
constexpr uint32_t OFF_A = 0;
constexpr uint32_t OFF_W = 3 * A_STAGE;         // 30720
constexpr uint32_t SMEM_TOTAL = OFF_W + 3 * W_STAGE;  // 61440 -> 3 CTAs/SM
}  // namespace cfg

// W transposed to fp16 [n][k].
__device__ __half g_Wh[cfg::NDIM * cfg::KDIM];

// ---------------- helpers ----------------
__device__ __forceinline__ uint32_t smem_u32(const void* p) {
    uint32_t a;
    asm("{ .reg .u64 t; cvta.to.shared.u64 t, %1; cvt.u32.u64 %0, t; }" : "=r"(a) : "l"(p));
    return a;
}
__device__ __forceinline__ void cp_async16(uint32_t dst, const void* src) {
    asm volatile("cp.async.cg.shared.global [%0], [%1], 16;" :: "r"(dst), "l"(src));
}
__device__ __forceinline__ void cp_commit() { asm volatile("cp.async.commit_group;"); }
template <int N>
__device__ __forceinline__ void cp_wait() {
    asm volatile("cp.async.wait_group %0;" :: "n"(N) : "memory");
}
__device__ __forceinline__ void ldsm_x4(uint32_t* r, uint32_t addr) {
    asm volatile("ldmatrix.sync.aligned.m8n8.x4.shared.b16 {%0,%1,%2,%3}, [%4];"
                 : "=r"(r[0]), "=r"(r[1]), "=r"(r[2]), "=r"(r[3]) : "r"(addr));
}
__device__ __forceinline__ float2 lds64(uint32_t addr) {
    float2 v;
    asm volatile("ld.shared.v2.f32 {%0,%1}, [%2];" : "=f"(v.x), "=f"(v.y) : "r"(addr));
    return v;
}
__device__ __forceinline__ void mma_f16(float* c, const uint32_t* a, const uint32_t* b) {
    asm volatile(
        "mma.sync.aligned.m16n8k16.row.col.f32.f16.f16.f32 "
        "{%0,%1,%2,%3}, {%4,%5,%6,%7}, {%8,%9}, {%0,%1,%2,%3};"
        : "+f"(c[0]), "+f"(c[1]), "+f"(c[2]), "+f"(c[3])
        : "r"(a[0]), "r"(a[1]), "r"(a[2]), "r"(a[3]), "r"(b[0]), "r"(b[1]));
}
// pack two fp32 -> one fp16x2 (lo = x, hi = y), round-to-nearest
__device__ __forceinline__ uint32_t cvt_f16x2(float2 v) {
    uint32_t r;
    asm("cvt.rn.f16x2.f32 %0, %1, %2;" : "=r"(r) : "f"(v.y), "f"(v.x));
    return r;
}

// ---------------- kernels ----------------

__global__ void gat_prep_w(const float* __restrict__ W) {
    using namespace cfg;
    int idx = blockIdx.x * blockDim.x + threadIdx.x;  // 65536
    int k = idx >> 8, n = idx & 255;
    g_Wh[n * KDIM + k] = __float2half_rn(W[idx]);
}

__global__ __launch_bounds__(cfg::NT, 3)
void gat_mma_gemm(const float* __restrict__ A, float* __restrict__ C) {
    using namespace cfg;
    extern __shared__ char smem[];
    const uint32_t sb = smem_u32(smem);

    const int tid = threadIdx.x;
    const int wid = tid >> 5, lane = tid & 31;
    const int warp_m = wid & 3;        // 4 x 16 rows
    const int warp_n = wid >> 2;       // 2 x 64 cols
    const size_t rowBase = (size_t)blockIdx.y * BM;
    const int colBase = blockIdx.x * BN;

    // A cp.async: 64 rows x 8 segs(16B) = 512 segs, 2 per thread
    const int aRowLd = tid >> 2;               // 0..63
    const int aSegLd = (tid & 3) * 2;          // segs {0..7} in pairs
    // W cp.async: 128 rows x 4 segs = 512 segs, 2 per thread
    const int wRowLd = tid >> 1;               // 0..127
    const int wSegLd = (tid & 1) * 2;

    auto cp_A = [&](int c) {           // one commit group
        const uint32_t base = sb + OFF_A + (uint32_t)(c % 3) * A_STAGE
                            + (uint32_t)aRowLd * A_STRIDE_B;
        const float* src = A + (rowBase + aRowLd) * KDIM + c * KC;
#pragma unroll
        for (int i = 0; i < 2; i++)
            cp_async16(base + (aSegLd + i) * 16, src + (aSegLd + i) * 4);
        cp_commit();
    };
    auto cp_W = [&](int c) {           // one commit group
        const uint32_t base = sb + OFF_W + (uint32_t)(c % 3) * W_STAGE
                            + (uint32_t)wRowLd * W_STRIDE_B;
        const __half* src = g_Wh + (size_t)(colBase + wRowLd) * KDIM + c * KC;
#pragma unroll
        for (int i = 0; i < 2; i++)
            cp_async16(base + (wSegLd + i) * 16, src + (wSegLd + i) * 8);
        cp_commit();
    };

    // prologue: groups A0,W0,A1,W1; force A0,W0; A1,W1 may still fly
    cp_A(0); cp_W(0);
    cp_A(1); cp_W(1);
    cp_wait<2>();
    __syncthreads();

    // per-lane fragment address components
    const uint32_t aOff = (uint32_t)(warp_m * 16 + (lane >> 2)) * A_STRIDE_B + (lane & 3) * 8;
    const uint32_t wRow = (uint32_t)(warp_n * 64 + (lane & 15));
    const uint32_t wKo = (uint32_t)((lane >> 4) << 3);  // elems

    float acc[8][4];
#pragma unroll
    for (int n = 0; n < 8; n++)
#pragma unroll
        for (int q = 0; q < 4; q++) acc[n][q] = 0.0f;

#pragma unroll 1
    for (int c = 0; c < NCHUNK; c++) {
        // depth-2 prefetch; stage (c+2)%3 was last read by compute(c-1),
        // which finished before the barrier ending iter c-1.
        if (c + 2 < NCHUNK) { cp_A(c + 2); cp_W(c + 2); }

        const uint32_t aBase = sb + OFF_A + (uint32_t)(c % 3) * A_STAGE + aOff;
        const uint32_t wBase = sb + OFF_W + (uint32_t)(c % 3) * W_STAGE;

#pragma unroll
        for (int s = 0; s < 2; s++) {
            // --- A fragment (16x16): 4 x LDS.64 + 4 x cvt ---
            uint32_t aF[4];
            {
                const uint32_t b0 = aBase + (uint32_t)s * 64;
                aF[0] = cvt_f16x2(lds64(b0));
                aF[1] = cvt_f16x2(lds64(b0 + 8 * A_STRIDE_B));
                aF[2] = cvt_f16x2(lds64(b0 + 32));
                aF[3] = cvt_f16x2(lds64(b0 + 8 * A_STRIDE_B + 32));
            }
            const uint32_t kcol = (uint32_t)(s * 16) + wKo;
            // 8 n-tiles (64 cols)
            uint32_t bF[8][2];
#pragma unroll
            for (int p = 0; p < 4; p++) {
                uint32_t r[4];
                ldsm_x4(r, wBase + (wRow + p * 16) * W_STRIDE_B + kcol * 2);
                bF[2 * p][0] = r[0]; bF[2 * p][1] = r[2];
                bF[2 * p + 1][0] = r[1]; bF[2 * p + 1][1] = r[3];
            }
#pragma unroll
            for (int n = 0; n < 8; n++) mma_f16(acc[n], aF, bF[n]);
        }

        if (c + 1 < NCHUNK) {
            if (c + 2 < NCHUNK) cp_wait<2>();  // chunk c+1 landed; newest 2 fly
            else cp_wait<0>();                 // tail
            __syncthreads();
        }
    }

    // ---- epilogue: warp -> rows warp_m*16..+15, cols warp_n*64..+63 ----
    const int g = lane >> 2, tg = lane & 3;
    const size_t m0 = rowBase + warp_m * 16 + g;
#pragma unroll
    for (int n = 0; n < 8; n++) {
        const int col = colBase + warp_n * 64 + n * 8 + tg * 2;
        *reinterpret_cast<float2*>(C + m0 * NDIM + col) =
            make_float2(acc[n][0], acc[n][1]);
        *reinterpret_cast<float2*>(C + (m0 + 8) * NDIM + col) =
            make_float2(acc[n][2], acc[n][3]);
    }
}

extern "C" void kernel_launch(void* const* d_in, const int* in_sizes, int n_in,
                              void* d_out, int out_size) {
    using namespace cfg;
    const float* A = (const float*)d_in[0];   // inputs [B,T,K] -> [M, 256]
    const float* W = (const float*)d_in[1];   // W [256, 256]
    float* C = (float*)d_out;

    const int M = in_sizes[0] / KDIM;         // 131072

    cudaFuncSetAttribute(gat_mma_gemm, cudaFuncAttributeMaxDynamicSharedMemorySize, SMEM_TOTAL);

    gat_prep_w<<<(KDIM * NDIM) / 256, 256>>>(W);
    dim3 grid(NDIM / BN, M / BM);
    gat_mma_gemm<<<grid, NT, SMEM_TOTAL>>>(A, C);
}